// round 4
// baseline (speedup 1.0000x reference)
#include <cuda_runtime.h>
#include <cstdint>
#include <math.h>

#define Bdim 4
#define Sdim 2048
#define Ddim 512
#define Hdim 8

// Scratch (device globals: allocation-free)
__device__ float g_q[(size_t)Bdim * Hdim * Sdim * Ddim];   // [b][h][s][e]
__device__ float g_k[(size_t)Bdim * Hdim * Sdim * Ddim];   // [b][h][t][e]
__device__ float g_v[(size_t)Bdim * Hdim * Sdim * Ddim];   // V^T: [b][h][e][t]
__device__ float g_p[(size_t)Bdim * Hdim * Sdim * Sdim];   // [b][h][s][t]
__device__ float g_c[(size_t)Bdim * Sdim * Hdim * Ddim];   // concat [b][s][h*D+e]

// ---------------- tf32 mma.sync GEMM (all-NT) ----------------
// C[M,N] = alpha * A[M,K] * B^T   (A: [M][K] row-major, B: [N][K] row-major)
// CTA 128x128, 128 threads (4 warps 2x2), warp tile 64x64.
// K-chunk 32 floats. 3-stage smem pipeline; tiles stored as tf32
// (cvt at staging), 128B rows with XOR-16B-chunk swizzle (chunk ^= row&7).
// Fragments loaded with ldmatrix.m8n8.x4.b16 (conflict-free).

#define BUFS   32768                       // A tile 16KB + B tile 16KB
#define SM_TOTAL (3 * BUFS)                // 98304 bytes

__device__ __forceinline__ uint32_t smem_u32(const void* p) {
    uint32_t a;
    asm("{ .reg .u64 t; cvta.to.shared.u64 t, %1; cvt.u32.u64 %0, t; }"
        : "=r"(a) : "l"(p));
    return a;
}

__device__ __forceinline__ uint32_t f2tf(float f) {
    uint32_t r;
    asm("cvt.rna.tf32.f32 %0, %1;" : "=r"(r) : "f"(f));
    return r;
}

__device__ __forceinline__ void mma8(float* c, const uint32_t* a,
                                     uint32_t b0, uint32_t b1) {
    asm volatile(
        "mma.sync.aligned.m16n8k8.row.col.f32.tf32.tf32.f32 "
        "{%0,%1,%2,%3}, {%4,%5,%6,%7}, {%8,%9}, {%0,%1,%2,%3};\n"
        : "+f"(c[0]), "+f"(c[1]), "+f"(c[2]), "+f"(c[3])
        : "r"(a[0]), "r"(a[1]), "r"(a[2]), "r"(a[3]), "r"(b0), "r"(b1));
}

__device__ __forceinline__ void ldm_x4(uint32_t* r, uint32_t addr) {
    asm volatile(
        "ldmatrix.sync.aligned.m8n8.x4.shared.b16 {%0,%1,%2,%3}, [%4];"
        : "=r"(r[0]), "=r"(r[1]), "=r"(r[2]), "=r"(r[3]) : "r"(addr));
}

// 128 rows x 32 floats: LDG 8 x float4 per thread
__device__ __forceinline__ void ldg8(float4* pa, const float* __restrict__ g,
                                     long ld, int kofs, int tid) {
#pragma unroll
    for (int i = 0; i < 8; i++) {
        const int idx = tid + i * 128;
        const int m = idx >> 3, ch = idx & 7;
        pa[i] = *(const float4*)(g + (long)m * ld + kofs + ch * 4);
    }
}

// cvt to tf32 + swizzled STS.128
__device__ __forceinline__ void sts8(uint32_t sbuf, const float4* pa, int tid) {
#pragma unroll
    for (int i = 0; i < 8; i++) {
        const int idx = tid + i * 128;
        const int m = idx >> 3, ch = idx & 7;
        const int sc = ch ^ (m & 7);
        asm volatile("st.shared.v4.b32 [%0], {%1,%2,%3,%4};"
                     :: "r"(sbuf + (uint32_t)(m * 128 + sc * 16)),
                        "r"(f2tf(pa[i].x)), "r"(f2tf(pa[i].y)),
                        "r"(f2tf(pa[i].z)), "r"(f2tf(pa[i].w)) : "memory");
    }
}

__global__ void __launch_bounds__(128, 2)
gemm_tc(const float* __restrict__ A, const float* __restrict__ Bm,
        float* __restrict__ C,
        int K, int lda, int ldb, int ldc, int Z2,
        long sA1, long sA2, long sB1, long sB2, long sC1, long sC2,
        float alpha)
{
    extern __shared__ float smem[];
    const uint32_t sb = smem_u32(smem);
    const int tid = threadIdx.x;
    const int wid = tid >> 5, lane = tid & 31;
    const int j = lane >> 3, rr = lane & 7;
    const int jlo = j & 1, jhi = j >> 1;
    const int wm = (wid & 1) * 64, wn = (wid >> 1) * 64;

    // per-lane ldmatrix row offsets (bytes)
    uint32_t rowA[4], rowB[4];
#pragma unroll
    for (int t = 0; t < 4; t++) {
        rowA[t] = (uint32_t)(wm + t * 16 + jlo * 8 + rr) * 128u;
        rowB[t] = (uint32_t)(wn + t * 16 + jlo * 8 + rr) * 128u + 16384u;
    }

    const int z = blockIdx.z, z1 = z / Z2, z2 = z % Z2;
    A  += z1 * sA1 + z2 * sA2;
    Bm += z1 * sB1 + z2 * sB2;
    C  += z1 * sC1 + z2 * sC2;
    const int bm = blockIdx.y * 128;
    const int bn = blockIdx.x * 128;

    const float* Ag = A + (long)bm * lda;
    const float* Bg = Bm + (long)bn * ldb;

    float acc[4][8][4];
#pragma unroll
    for (int mt = 0; mt < 4; mt++)
#pragma unroll
        for (int nt = 0; nt < 8; nt++)
#pragma unroll
            for (int q = 0; q < 4; q++) acc[mt][nt][q] = 0.f;

    const int KC = K >> 5;

    // prologue: stage chunks 0,1 into buffers 0,1
    {
        float4 pa[8];
        ldg8(pa, Ag, lda, 0, tid);  sts8(sb, pa, tid);
        ldg8(pa, Bg, ldb, 0, tid);  sts8(sb + 16384u, pa, tid);
        ldg8(pa, Ag, lda, 32, tid); sts8(sb + BUFS, pa, tid);
        ldg8(pa, Bg, ldb, 32, tid); sts8(sb + BUFS + 16384u, pa, tid);
    }
    __syncthreads();

    int bufc = 0;
    for (int c = 0; c < KC; c++) {
        const uint32_t ab = sb + (uint32_t)bufc * BUFS;
        int si = bufc + 2; if (si >= 3) si -= 3;
        const uint32_t sstage = sb + (uint32_t)si * BUFS;
        const bool st = (c + 2 < KC);

        float4 pa[8];
        if (st) ldg8(pa, Ag, lda, (c + 2) * 32, tid);

#pragma unroll
        for (int ks = 0; ks < 2; ks++) {
            const uint32_t sc16 = (uint32_t)(((2 * ks + jhi) ^ rr) * 16);
            uint32_t a[4][4], b[4][4];
#pragma unroll
            for (int mt = 0; mt < 4; mt++) ldm_x4(a[mt], ab + rowA[mt] + sc16);
#pragma unroll
            for (int np = 0; np < 4; np++) ldm_x4(b[np], ab + rowB[np] + sc16);
#pragma unroll
            for (int mt = 0; mt < 4; mt++)
#pragma unroll
                for (int np = 0; np < 4; np++) {
                    mma8(acc[mt][2 * np],     a[mt], b[np][0], b[np][2]);
                    mma8(acc[mt][2 * np + 1], a[mt], b[np][1], b[np][3]);
                }
        }

        if (st) { sts8(sstage, pa, tid); ldg8(pa, Bg, ldb, (c + 2) * 32, tid); }

#pragma unroll
        for (int ks = 2; ks < 4; ks++) {
            const uint32_t sc16 = (uint32_t)(((2 * ks + jhi) ^ rr) * 16);
            uint32_t a[4][4], b[4][4];
#pragma unroll
            for (int mt = 0; mt < 4; mt++) ldm_x4(a[mt], ab + rowA[mt] + sc16);
#pragma unroll
            for (int np = 0; np < 4; np++) ldm_x4(b[np], ab + rowB[np] + sc16);
#pragma unroll
            for (int mt = 0; mt < 4; mt++)
#pragma unroll
                for (int np = 0; np < 4; np++) {
                    mma8(acc[mt][2 * np],     a[mt], b[np][0], b[np][2]);
                    mma8(acc[mt][2 * np + 1], a[mt], b[np][1], b[np][3]);
                }
        }

        if (st) sts8(sstage + 16384u, pa, tid);
        __syncthreads();
        bufc++; if (bufc == 3) bufc = 0;
    }

    // epilogue: STG.64 pairs
    const int g = lane >> 2, t4 = lane & 3;
#pragma unroll
    for (int mt = 0; mt < 4; mt++) {
#pragma unroll
        for (int nt = 0; nt < 8; nt++) {
            const int r0 = bm + wm + mt * 16 + g;
            const int c0 = bn + wn + nt * 8 + t4 * 2;
            float2 v0 = make_float2(alpha * acc[mt][nt][0], alpha * acc[mt][nt][1]);
            float2 v1 = make_float2(alpha * acc[mt][nt][2], alpha * acc[mt][nt][3]);
            *(float2*)&C[(long)r0 * ldc + c0] = v0;
            *(float2*)&C[(long)(r0 + 8) * ldc + c0] = v1;
        }
    }
}

// ---------------- masked softmax ----------------
__global__ void softmax_kernel(float* __restrict__ P, const int* __restrict__ mask)
{
    const int row = blockIdx.x;            // (b*H + h)*S + i
    const int b = row >> 14;               // / (H*S = 16384)
    const int i = row & (Sdim - 1);
    float* p = P + (size_t)row * Sdim;
    const int* mb = mask + b * Sdim;
    const int mi = mb[i];
    const int tid = threadIdx.x;

    float v[8];
    float mx = -1e30f;
#pragma unroll
    for (int l = 0; l < 8; l++) {
        const int j = tid + l * 256;
        float x = p[j];
        if (!(mi * mb[j] > 0)) x = -1e9f;
        v[l] = x;
        mx = fmaxf(mx, x);
    }

    __shared__ float red[32];
    for (int o = 16; o > 0; o >>= 1) mx = fmaxf(mx, __shfl_xor_sync(0xffffffffu, mx, o));
    if ((tid & 31) == 0) red[tid >> 5] = mx;
    __syncthreads();
    if (tid < 32) {
        float m2 = (tid < 8) ? red[tid] : -1e30f;
        for (int o = 4; o > 0; o >>= 1) m2 = fmaxf(m2, __shfl_xor_sync(0xffffffffu, m2, o));
        if (tid == 0) red[0] = m2;
    }
    __syncthreads();
    mx = red[0];
    __syncthreads();

    float s = 0.f;
#pragma unroll
    for (int l = 0; l < 8; l++) {
        const float e = expf(v[l] - mx);
        v[l] = e;
        s += e;
    }
    for (int o = 16; o > 0; o >>= 1) s += __shfl_xor_sync(0xffffffffu, s, o);
    if ((tid & 31) == 0) red[tid >> 5] = s;
    __syncthreads();
    if (tid < 32) {
        float s2 = (tid < 8) ? red[tid] : 0.f;
        for (int o = 4; o > 0; o >>= 1) s2 += __shfl_xor_sync(0xffffffffu, s2, o);
        if (tid == 0) red[0] = s2;
    }
    __syncthreads();
    const float inv = 1.0f / red[0];
#pragma unroll
    for (int l = 0; l < 8; l++) p[tid + l * 256] = v[l] * inv;
}

// ---------------- launcher ----------------
extern "C" void kernel_launch(void* const* d_in, const int* in_sizes, int n_in,
                              void* d_out, int out_size)
{
    (void)in_sizes; (void)n_in; (void)out_size;
    const float* x    = (const float*)d_in[0];
    const int*   mask = (const int*)d_in[1];
    const float* Wq   = (const float*)d_in[2];
    const float* Wk   = (const float*)d_in[3];
    const float* Wv   = (const float*)d_in[4];
    const float* Wp   = (const float*)d_in[5];
    float* out = (float*)d_out;

    float *q, *k, *v, *p, *c;
    cudaGetSymbolAddress((void**)&q, g_q);
    cudaGetSymbolAddress((void**)&k, g_k);
    cudaGetSymbolAddress((void**)&v, g_v);
    cudaGetSymbolAddress((void**)&p, g_p);
    cudaGetSymbolAddress((void**)&c, g_c);

    cudaFuncSetAttribute(gemm_tc, cudaFuncAttributeMaxDynamicSharedMemorySize, SM_TOTAL);

    const long SD = (long)Sdim * Ddim;      // 1048576
    const long DD = (long)Ddim * Ddim;      // 262144
    const long SS = (long)Sdim * Sdim;      // 4194304
    const float scale = 1.0f / sqrtf((float)Ddim);
    dim3 blk(128);

    // 1) Q,K projections: per (h,b): q[b,h,s,e] = x[b] @ Wq[h]^T
    {
        dim3 grid(Ddim / 128, Sdim / 128, Hdim * Bdim);
        gemm_tc<<<grid, blk, SM_TOTAL>>>(x, Wq, q, Ddim, Ddim, Ddim, Ddim, Bdim,
                                         0, SD, DD, 0, SD, Hdim * SD, 1.f);
        gemm_tc<<<grid, blk, SM_TOTAL>>>(x, Wk, k, Ddim, Ddim, Ddim, Ddim, Bdim,
                                         0, SD, DD, 0, SD, Hdim * SD, 1.f);
    }

    // 2) V^T: v_t[b,h,e,t] = Wv[h] @ x[b]^T : M=D(e), N=S(t), K=D
    {
        dim3 grid(Sdim / 128, Ddim / 128, Hdim * Bdim);
        gemm_tc<<<grid, blk, SM_TOTAL>>>(Wv, x, v, Ddim, Ddim, Ddim, Sdim, Bdim,
                                         DD, 0, 0, SD, SD, Hdim * SD, 1.f);
    }

    // 3) logits: L[s,t] = scale * q[b,h] @ k[b,h]^T : M=N=S, K=D ; z=b*H+h
    {
        dim3 grid(Sdim / 128, Sdim / 128, Bdim * Hdim);
        gemm_tc<<<grid, blk, SM_TOTAL>>>(q, k, p, Ddim, Ddim, Ddim, Sdim, 1,
                                         SD, 0, SD, 0, SS, 0, scale);
    }

    // 4) masked softmax in place
    softmax_kernel<<<Bdim * Hdim * Sdim, 256>>>(p, mask);

    // 5) PV: O[s,e] = P[b,h] @ v_t[b,h]^T : M=S, N=D, K=S -> concat layout
    {
        dim3 grid(Ddim / 128, Sdim / 128, Bdim * Hdim);
        gemm_tc<<<grid, blk, SM_TOTAL>>>(p, v, c, Sdim, Sdim, Sdim, Hdim * Ddim, Hdim,
                                         (long)Hdim * SS, SS, (long)Hdim * SD, SD,
                                         (long)Sdim * Hdim * Ddim, (long)Ddim, 1.f);
    }

    // 6) out proj: y[b,s,d] = cat[b] @ Wp^T : M=S, N=D, K=H*D ; z=b
    {
        dim3 grid(Ddim / 128, Sdim / 128, Bdim);
        gemm_tc<<<grid, blk, SM_TOTAL>>>(c, Wp, out, Hdim * Ddim,
                                         Hdim * Ddim, Hdim * Ddim, Ddim, 1,
                                         (long)Sdim * Hdim * Ddim, 0, 0, 0,
                                         SD, 0, 1.f);
    }
}

// round 5
// speedup vs baseline: 1.2033x; 1.2033x over previous
#include <cuda_runtime.h>
#include <cstdint>
#include <math.h>

#define Bdim 4
#define Sdim 2048
#define Ddim 512
#define Hdim 8

// Scratch (device globals: allocation-free)
__device__ float g_q[(size_t)Bdim * Hdim * Sdim * Ddim];   // [b][h][s][e]
__device__ float g_k[(size_t)Bdim * Hdim * Sdim * Ddim];   // [b][h][t][e]
__device__ float g_v[(size_t)Bdim * Hdim * Sdim * Ddim];   // V^T: [b][h][e][t]
__device__ float g_p[(size_t)Bdim * Hdim * Sdim * Sdim];   // [b][h][s][t]
__device__ float g_c[(size_t)Bdim * Sdim * Hdim * Ddim];   // concat [b][s][h*D+e]

// ---------------- tf32 mma.sync GEMM (all-NT) ----------------
// C[M,N] = alpha * A[M,K] * B^T   (A: [M][K] row-major, B: [N][K] row-major)
// CTA 128x128, 128 threads (4 warps 2x2), warp tile 64x64.
// K-chunk 32 floats. 3-stage cp.async pipeline (raw fp32 in smem),
// XOR-16B-chunk swizzle (chunk ^= row&7), ldmatrix.x4 fragment loads,
// cvt.rna.tf32 applied on fragments (numerics identical to R2/R3).

#define BUFS   32768                       // A tile 16KB + B tile 16KB
#define SM_TOTAL (3 * BUFS)                // 98304 bytes

__device__ __forceinline__ uint32_t smem_u32(const void* p) {
    uint32_t a;
    asm("{ .reg .u64 t; cvta.to.shared.u64 t, %1; cvt.u32.u64 %0, t; }"
        : "=r"(a) : "l"(p));
    return a;
}

__device__ __forceinline__ uint32_t f2tf_bits(uint32_t bits) {
    uint32_t r;
    asm("cvt.rna.tf32.f32 %0, %1;" : "=r"(r) : "f"(__uint_as_float(bits)));
    return r;
}

__device__ __forceinline__ void cpasync16(uint32_t dst, const void* src) {
    asm volatile("cp.async.cg.shared.global [%0], [%1], 16;"
                 :: "r"(dst), "l"(src) : "memory");
}

__device__ __forceinline__ void mma8(float* c, const uint32_t* a,
                                     uint32_t b0, uint32_t b1) {
    asm volatile(
        "mma.sync.aligned.m16n8k8.row.col.f32.tf32.tf32.f32 "
        "{%0,%1,%2,%3}, {%4,%5,%6,%7}, {%8,%9}, {%0,%1,%2,%3};\n"
        : "+f"(c[0]), "+f"(c[1]), "+f"(c[2]), "+f"(c[3])
        : "r"(a[0]), "r"(a[1]), "r"(a[2]), "r"(a[3]), "r"(b0), "r"(b1));
}

__device__ __forceinline__ void ldm_x4(uint32_t* r, uint32_t addr) {
    asm volatile(
        "ldmatrix.sync.aligned.m8n8.x4.shared.b16 {%0,%1,%2,%3}, [%4];"
        : "=r"(r[0]), "=r"(r[1]), "=r"(r[2]), "=r"(r[3]) : "r"(addr));
}

// stage one 128x32 fp32 tile via 8 cp.async.16B per thread (swizzled dst)
__device__ __forceinline__ void stage_cp(uint32_t sbuf, const float* __restrict__ g,
                                         long ld, int kofs, int tid) {
#pragma unroll
    for (int i = 0; i < 8; i++) {
        const int idx = tid + i * 128;
        const int m = idx >> 3, ch = idx & 7;
        const int sc = ch ^ (m & 7);
        cpasync16(sbuf + (uint32_t)(m * 128 + sc * 16),
                  g + (long)m * ld + kofs + ch * 4);
    }
}

__global__ void __launch_bounds__(128, 2)
gemm_tc(const float* __restrict__ A, const float* __restrict__ Bm,
        float* __restrict__ C,
        int K, int lda, int ldb, int ldc, int Z2,
        long sA1, long sA2, long sB1, long sB2, long sC1, long sC2,
        float alpha)
{
    extern __shared__ float smem[];
    const uint32_t sb = smem_u32(smem);
    const int tid = threadIdx.x;
    const int wid = tid >> 5, lane = tid & 31;
    const int j = lane >> 3, rr = lane & 7;
    const int jlo = j & 1, jhi = j >> 1;
    const int wm = (wid & 1) * 64, wn = (wid >> 1) * 64;

    // per-lane ldmatrix row offsets (bytes within a buffer)
    uint32_t rowA[4], rowB[4];
#pragma unroll
    for (int t = 0; t < 4; t++) {
        rowA[t] = (uint32_t)(wm + t * 16 + jlo * 8 + rr) * 128u;
        rowB[t] = (uint32_t)(wn + t * 16 + jlo * 8 + rr) * 128u + 16384u;
    }

    const int z = blockIdx.z, z1 = z / Z2, z2 = z % Z2;
    A  += z1 * sA1 + z2 * sA2;
    Bm += z1 * sB1 + z2 * sB2;
    C  += z1 * sC1 + z2 * sC2;
    const int bm = blockIdx.y * 128;
    const int bn = blockIdx.x * 128;

    const float* Ag = A + (long)bm * lda;
    const float* Bg = Bm + (long)bn * ldb;

    float acc[4][8][4];
#pragma unroll
    for (int mt = 0; mt < 4; mt++)
#pragma unroll
        for (int nt = 0; nt < 8; nt++)
#pragma unroll
            for (int q = 0; q < 4; q++) acc[mt][nt][q] = 0.f;

    const int KC = K >> 5;

    // prologue: stage chunks 0,1 into buffers 0,1 (two commit groups)
    stage_cp(sb,               Ag, lda, 0, tid);
    stage_cp(sb + 16384u,      Bg, ldb, 0, tid);
    asm volatile("cp.async.commit_group;" ::: "memory");
    stage_cp(sb + BUFS,          Ag, lda, 32, tid);
    stage_cp(sb + BUFS + 16384u, Bg, ldb, 32, tid);
    asm volatile("cp.async.commit_group;" ::: "memory");

    int bufc = 0;
    for (int c = 0; c < KC; c++) {
        if (c + 1 < KC)
            asm volatile("cp.async.wait_group 1;" ::: "memory");
        else
            asm volatile("cp.async.wait_group 0;" ::: "memory");
        __syncthreads();

        // stage chunk c+2 into buffer (bufc+2)%3 (not being read this iter)
        if (c + 2 < KC) {
            int si = bufc + 2; if (si >= 3) si -= 3;
            const uint32_t ss = sb + (uint32_t)si * BUFS;
            stage_cp(ss,           Ag, lda, (c + 2) * 32, tid);
            stage_cp(ss + 16384u,  Bg, ldb, (c + 2) * 32, tid);
        }
        asm volatile("cp.async.commit_group;" ::: "memory");

        const uint32_t ab = sb + (uint32_t)bufc * BUFS;
#pragma unroll
        for (int ks = 0; ks < 4; ks++) {
            const uint32_t sc16 = (uint32_t)(((2 * ks + jhi) ^ rr) * 16);
            uint32_t a[4][4], b[4][4];
#pragma unroll
            for (int mt = 0; mt < 4; mt++) ldm_x4(a[mt], ab + rowA[mt] + sc16);
#pragma unroll
            for (int np = 0; np < 4; np++) ldm_x4(b[np], ab + rowB[np] + sc16);
            // tf32 round on fragments
#pragma unroll
            for (int mt = 0; mt < 4; mt++)
#pragma unroll
                for (int q = 0; q < 4; q++) a[mt][q] = f2tf_bits(a[mt][q]);
#pragma unroll
            for (int np = 0; np < 4; np++)
#pragma unroll
                for (int q = 0; q < 4; q++) b[np][q] = f2tf_bits(b[np][q]);
#pragma unroll
            for (int mt = 0; mt < 4; mt++)
#pragma unroll
                for (int np = 0; np < 4; np++) {
                    mma8(acc[mt][2 * np],     a[mt], b[np][0], b[np][2]);
                    mma8(acc[mt][2 * np + 1], a[mt], b[np][1], b[np][3]);
                }
        }
        bufc++; if (bufc == 3) bufc = 0;
    }

    // epilogue: STG.64 pairs
    const int g = lane >> 2, t4 = lane & 3;
#pragma unroll
    for (int mt = 0; mt < 4; mt++) {
#pragma unroll
        for (int nt = 0; nt < 8; nt++) {
            const int r0 = bm + wm + mt * 16 + g;
            const int c0 = bn + wn + nt * 8 + t4 * 2;
            float2 v0 = make_float2(alpha * acc[mt][nt][0], alpha * acc[mt][nt][1]);
            float2 v1 = make_float2(alpha * acc[mt][nt][2], alpha * acc[mt][nt][3]);
            *(float2*)&C[(long)r0 * ldc + c0] = v0;
            *(float2*)&C[(long)(r0 + 8) * ldc + c0] = v1;
        }
    }
}

// ---------------- masked softmax ----------------
__global__ void softmax_kernel(float* __restrict__ P, const int* __restrict__ mask)
{
    const int row = blockIdx.x;            // (b*H + h)*S + i
    const int b = row >> 14;               // / (H*S = 16384)
    const int i = row & (Sdim - 1);
    float* p = P + (size_t)row * Sdim;
    const int* mb = mask + b * Sdim;
    const int mi = mb[i];
    const int tid = threadIdx.x;

    float v[8];
    float mx = -1e30f;
#pragma unroll
    for (int l = 0; l < 8; l++) {
        const int j = tid + l * 256;
        float x = p[j];
        if (!(mi * mb[j] > 0)) x = -1e9f;
        v[l] = x;
        mx = fmaxf(mx, x);
    }

    __shared__ float red[32];
    for (int o = 16; o > 0; o >>= 1) mx = fmaxf(mx, __shfl_xor_sync(0xffffffffu, mx, o));
    if ((tid & 31) == 0) red[tid >> 5] = mx;
    __syncthreads();
    if (tid < 32) {
        float m2 = (tid < 8) ? red[tid] : -1e30f;
        for (int o = 4; o > 0; o >>= 1) m2 = fmaxf(m2, __shfl_xor_sync(0xffffffffu, m2, o));
        if (tid == 0) red[0] = m2;
    }
    __syncthreads();
    mx = red[0];
    __syncthreads();

    float s = 0.f;
#pragma unroll
    for (int l = 0; l < 8; l++) {
        const float e = expf(v[l] - mx);
        v[l] = e;
        s += e;
    }
    for (int o = 16; o > 0; o >>= 1) s += __shfl_xor_sync(0xffffffffu, s, o);
    if ((tid & 31) == 0) red[tid >> 5] = s;
    __syncthreads();
    if (tid < 32) {
        float s2 = (tid < 8) ? red[tid] : 0.f;
        for (int o = 4; o > 0; o >>= 1) s2 += __shfl_xor_sync(0xffffffffu, s2, o);
        if (tid == 0) red[0] = s2;
    }
    __syncthreads();
    const float inv = 1.0f / red[0];
#pragma unroll
    for (int l = 0; l < 8; l++) p[tid + l * 256] = v[l] * inv;
}

// ---------------- launcher ----------------
extern "C" void kernel_launch(void* const* d_in, const int* in_sizes, int n_in,
                              void* d_out, int out_size)
{
    (void)in_sizes; (void)n_in; (void)out_size;
    const float* x    = (const float*)d_in[0];
    const int*   mask = (const int*)d_in[1];
    const float* Wq   = (const float*)d_in[2];
    const float* Wk   = (const float*)d_in[3];
    const float* Wv   = (const float*)d_in[4];
    const float* Wp   = (const float*)d_in[5];
    float* out = (float*)d_out;

    float *q, *k, *v, *p, *c;
    cudaGetSymbolAddress((void**)&q, g_q);
    cudaGetSymbolAddress((void**)&k, g_k);
    cudaGetSymbolAddress((void**)&v, g_v);
    cudaGetSymbolAddress((void**)&p, g_p);
    cudaGetSymbolAddress((void**)&c, g_c);

    cudaFuncSetAttribute(gemm_tc, cudaFuncAttributeMaxDynamicSharedMemorySize, SM_TOTAL);

    const long SD = (long)Sdim * Ddim;      // 1048576
    const long DD = (long)Ddim * Ddim;      // 262144
    const long SS = (long)Sdim * Sdim;      // 4194304
    const float scale = 1.0f / sqrtf((float)Ddim);
    dim3 blk(128);

    // 1) Q,K projections: per (h,b): q[b,h,s,e] = x[b] @ Wq[h]^T
    {
        dim3 grid(Ddim / 128, Sdim / 128, Hdim * Bdim);
        gemm_tc<<<grid, blk, SM_TOTAL>>>(x, Wq, q, Ddim, Ddim, Ddim, Ddim, Bdim,
                                         0, SD, DD, 0, SD, Hdim * SD, 1.f);
        gemm_tc<<<grid, blk, SM_TOTAL>>>(x, Wk, k, Ddim, Ddim, Ddim, Ddim, Bdim,
                                         0, SD, DD, 0, SD, Hdim * SD, 1.f);
    }

    // 2) V^T: v_t[b,h,e,t] = Wv[h] @ x[b]^T : M=D(e), N=S(t), K=D
    {
        dim3 grid(Sdim / 128, Ddim / 128, Hdim * Bdim);
        gemm_tc<<<grid, blk, SM_TOTAL>>>(Wv, x, v, Ddim, Ddim, Ddim, Sdim, Bdim,
                                         DD, 0, 0, SD, SD, Hdim * SD, 1.f);
    }

    // 3) logits: L[s,t] = scale * q[b,h] @ k[b,h]^T : M=N=S, K=D ; z=b*H+h
    {
        dim3 grid(Sdim / 128, Sdim / 128, Bdim * Hdim);
        gemm_tc<<<grid, blk, SM_TOTAL>>>(q, k, p, Ddim, Ddim, Ddim, Sdim, 1,
                                         SD, 0, SD, 0, SS, 0, scale);
    }

    // 4) masked softmax in place
    softmax_kernel<<<Bdim * Hdim * Sdim, 256>>>(p, mask);

    // 5) PV: O[s,e] = P[b,h] @ v_t[b,h]^T : M=S, N=D, K=S -> concat layout
    {
        dim3 grid(Ddim / 128, Sdim / 128, Bdim * Hdim);
        gemm_tc<<<grid, blk, SM_TOTAL>>>(p, v, c, Sdim, Sdim, Sdim, Hdim * Ddim, Hdim,
                                         (long)Hdim * SS, SS, (long)Hdim * SD, SD,
                                         (long)Sdim * Hdim * Ddim, (long)Ddim, 1.f);
    }

    // 6) out proj: y[b,s,d] = cat[b] @ Wp^T : M=S, N=D, K=H*D ; z=b
    {
        dim3 grid(Ddim / 128, Sdim / 128, Bdim);
        gemm_tc<<<grid, blk, SM_TOTAL>>>(c, Wp, out, Hdim * Ddim,
                                         Hdim * Ddim, Hdim * Ddim, Ddim, 1,
                                         (long)Sdim * Hdim * Ddim, 0, 0, 0,
                                         SD, 0, 1.f);
    }
}

// round 6
// speedup vs baseline: 1.6242x; 1.3498x over previous
#include <cuda_runtime.h>
#include <cuda_fp16.h>
#include <cstdint>
#include <math.h>

#define Bdim 4
#define Sdim 2048
#define Ddim 512
#define Hdim 8

// half scratch (device globals: allocation-free)
__device__ __half g_x [(size_t)Bdim * Sdim * Ddim];          // x in half
__device__ __half g_wq[(size_t)Hdim * Ddim * Ddim];
__device__ __half g_wk[(size_t)Hdim * Ddim * Ddim];
__device__ __half g_wv[(size_t)Hdim * Ddim * Ddim];
__device__ __half g_wp[(size_t)Ddim * Hdim * Ddim];
__device__ __half g_q [(size_t)Bdim * Hdim * Sdim * Ddim];   // [b][h][s][e]
__device__ __half g_k [(size_t)Bdim * Hdim * Sdim * Ddim];   // [b][h][t][e]
__device__ __half g_v [(size_t)Bdim * Hdim * Sdim * Ddim];   // V^T: [b][h][e][t]
__device__ __half g_p [(size_t)Bdim * Hdim * Sdim * Sdim];   // [b][h][s][t]
__device__ __half g_c [(size_t)Bdim * Sdim * Hdim * Ddim];   // concat

// ---------------- fp16 mma.sync GEMM (all-NT, fp32 accum) ----------------
// C[M,N] = alpha * A[M,K] * B^T   (A: [M][K] half, B: [N][K] half, K-contig)
// CTA 128x128, 4 warps (2x2), warp tile 64x64, K-chunk 64 halves (128B rows).
// 3-stage cp.async pipeline, XOR-16B swizzle, ldmatrix.x4 fragments,
// mma.m16n8k16.f16 with fp32 accumulators.

#define BUFS   32768                       // A tile 16KB + B tile 16KB
#define SM_TOTAL (3 * BUFS)                // 98304 bytes

__device__ __forceinline__ uint32_t smem_u32(const void* p) {
    uint32_t a;
    asm("{ .reg .u64 t; cvta.to.shared.u64 t, %1; cvt.u32.u64 %0, t; }"
        : "=r"(a) : "l"(p));
    return a;
}

__device__ __forceinline__ void cpasync16(uint32_t dst, const void* src) {
    asm volatile("cp.async.cg.shared.global [%0], [%1], 16;"
                 :: "r"(dst), "l"(src) : "memory");
}

__device__ __forceinline__ void mma16(float* c, const uint32_t* a,
                                      uint32_t b0, uint32_t b1) {
    asm volatile(
        "mma.sync.aligned.m16n8k16.row.col.f32.f16.f16.f32 "
        "{%0,%1,%2,%3}, {%4,%5,%6,%7}, {%8,%9}, {%0,%1,%2,%3};\n"
        : "+f"(c[0]), "+f"(c[1]), "+f"(c[2]), "+f"(c[3])
        : "r"(a[0]), "r"(a[1]), "r"(a[2]), "r"(a[3]), "r"(b0), "r"(b1));
}

__device__ __forceinline__ void ldm_x4(uint32_t* r, uint32_t addr) {
    asm volatile(
        "ldmatrix.sync.aligned.m8n8.x4.shared.b16 {%0,%1,%2,%3}, [%4];"
        : "=r"(r[0]), "=r"(r[1]), "=r"(r[2]), "=r"(r[3]) : "r"(addr));
}

// stage one 128row x 64half tile via 8 cp.async.16B per thread (swizzled)
__device__ __forceinline__ void stage_cp(uint32_t sbuf, const __half* __restrict__ g,
                                         long ld, int kofs, int tid) {
#pragma unroll
    for (int i = 0; i < 8; i++) {
        const int idx = tid + i * 128;
        const int m = idx >> 3, ch = idx & 7;
        const int sc = ch ^ (m & 7);
        cpasync16(sbuf + (uint32_t)(m * 128 + sc * 16),
                  g + (long)m * ld + kofs + ch * 8);
    }
}

__device__ __forceinline__ void store2(float* C, long off, float v0, float v1) {
    *(float2*)&C[off] = make_float2(v0, v1);
}
__device__ __forceinline__ void store2(__half* C, long off, float v0, float v1) {
    *(__half2*)&C[off] = __floats2half2_rn(v0, v1);
}

template <typename OutT>
__global__ void __launch_bounds__(128, 2)
gemm_h(const __half* __restrict__ A, const __half* __restrict__ Bm,
       OutT* __restrict__ C,
       int K, int lda, int ldb, int ldc, int Z2,
       long sA1, long sA2, long sB1, long sB2, long sC1, long sC2,
       float alpha)
{
    extern __shared__ __half smem[];
    const uint32_t sb = smem_u32(smem);
    const int tid = threadIdx.x;
    const int wid = tid >> 5, lane = tid & 31;
    const int g8 = lane >> 3, rr = lane & 7;
    const int wm = (wid & 1) * 64, wn = (wid >> 1) * 64;
    const int acs = g8 >> 1;       // A: +16B (k+8) selector
    const int bcs = g8 & 1;        // B: +16B (k+8) selector

    // per-lane ldmatrix row byte offsets within a buffer
    uint32_t rowA[4], rowB[4];
#pragma unroll
    for (int t = 0; t < 4; t++) {
        rowA[t] = (uint32_t)(wm + t * 16 + (g8 & 1) * 8 + rr) * 128u;
        rowB[t] = (uint32_t)(wn + t * 16 + (g8 >> 1) * 8 + rr) * 128u + 16384u;
    }

    const int z = blockIdx.z, z1 = z / Z2, z2 = z % Z2;
    A  += z1 * sA1 + z2 * sA2;
    Bm += z1 * sB1 + z2 * sB2;
    C  += z1 * sC1 + z2 * sC2;
    const int bm = blockIdx.y * 128;
    const int bn = blockIdx.x * 128;

    const __half* Ag = A + (long)bm * lda;
    const __half* Bg = Bm + (long)bn * ldb;

    float acc[4][8][4];
#pragma unroll
    for (int mt = 0; mt < 4; mt++)
#pragma unroll
        for (int nt = 0; nt < 8; nt++)
#pragma unroll
            for (int q = 0; q < 4; q++) acc[mt][nt][q] = 0.f;

    const int KC = K >> 6;                 // 64 halves per chunk

    // prologue: chunks 0,1 -> buffers 0,1
    stage_cp(sb,                 Ag, lda, 0, tid);
    stage_cp(sb + 16384u,        Bg, ldb, 0, tid);
    asm volatile("cp.async.commit_group;" ::: "memory");
    stage_cp(sb + BUFS,          Ag, lda, 64, tid);
    stage_cp(sb + BUFS + 16384u, Bg, ldb, 64, tid);
    asm volatile("cp.async.commit_group;" ::: "memory");

    int bufc = 0;
    for (int c = 0; c < KC; c++) {
        if (c + 1 < KC)
            asm volatile("cp.async.wait_group 1;" ::: "memory");
        else
            asm volatile("cp.async.wait_group 0;" ::: "memory");
        __syncthreads();

        if (c + 2 < KC) {
            int si = bufc + 2; if (si >= 3) si -= 3;
            const uint32_t ss = sb + (uint32_t)si * BUFS;
            stage_cp(ss,          Ag, lda, (c + 2) * 64, tid);
            stage_cp(ss + 16384u, Bg, ldb, (c + 2) * 64, tid);
        }
        asm volatile("cp.async.commit_group;" ::: "memory");

        const uint32_t ab = sb + (uint32_t)bufc * BUFS;
#pragma unroll
        for (int ks = 0; ks < 4; ks++) {
            const uint32_t sca = (uint32_t)(((2 * ks + acs) ^ rr) * 16);
            const uint32_t scb = (uint32_t)(((2 * ks + bcs) ^ rr) * 16);
            uint32_t a[4][4], b[4][4];
#pragma unroll
            for (int mt = 0; mt < 4; mt++) ldm_x4(a[mt], ab + rowA[mt] + sca);
#pragma unroll
            for (int np = 0; np < 4; np++) ldm_x4(b[np], ab + rowB[np] + scb);
#pragma unroll
            for (int mt = 0; mt < 4; mt++)
#pragma unroll
                for (int np = 0; np < 4; np++) {
                    mma16(acc[mt][2 * np],     a[mt], b[np][0], b[np][1]);
                    mma16(acc[mt][2 * np + 1], a[mt], b[np][2], b[np][3]);
                }
        }
        bufc++; if (bufc == 3) bufc = 0;
    }

    // epilogue
    const int g = lane >> 2, t4 = lane & 3;
#pragma unroll
    for (int mt = 0; mt < 4; mt++) {
#pragma unroll
        for (int nt = 0; nt < 8; nt++) {
            const int r0 = bm + wm + mt * 16 + g;
            const int c0 = bn + wn + nt * 8 + t4 * 2;
            store2(C, (long)r0 * ldc + c0,
                   alpha * acc[mt][nt][0], alpha * acc[mt][nt][1]);
            store2(C, (long)(r0 + 8) * ldc + c0,
                   alpha * acc[mt][nt][2], alpha * acc[mt][nt][3]);
        }
    }
}

// ---------------- fp32 -> fp16 convert ----------------
__global__ void f2h_kernel(const float* __restrict__ in, __half* __restrict__ out,
                           int n4)
{
    int i = blockIdx.x * 256 + threadIdx.x;
    if (i < n4) {
        float4 v = ((const float4*)in)[i];
        __half2 h0 = __floats2half2_rn(v.x, v.y);
        __half2 h1 = __floats2half2_rn(v.z, v.w);
        uint2 u;
        u.x = *(uint32_t*)&h0;
        u.y = *(uint32_t*)&h1;
        ((uint2*)out)[i] = u;
    }
}

// ---------------- masked softmax on half P ----------------
__global__ void softmax_h(__half* __restrict__ P, const int* __restrict__ mask)
{
    const int row = blockIdx.x;            // (b*H + h)*S + i
    const int b = row >> 14;               // / (H*S = 16384)
    const int i = row & (Sdim - 1);
    __half* p = P + (size_t)row * Sdim;
    const int* mb = mask + b * Sdim;
    const int mi = mb[i];
    const int tid = threadIdx.x;
    const int base = tid * 8;

    uint4 raw = ((const uint4*)p)[tid];
    __half2 hh[4];
    hh[0] = *(__half2*)&raw.x; hh[1] = *(__half2*)&raw.y;
    hh[2] = *(__half2*)&raw.z; hh[3] = *(__half2*)&raw.w;

    float v[8];
    float mx = -1e30f;
#pragma unroll
    for (int l = 0; l < 8; l++) {
        float2 f2 = __half22float2(hh[l >> 1]);
        float x = (l & 1) ? f2.y : f2.x;
        if (!(mi * mb[base + l] > 0)) x = -1e9f;
        v[l] = x;
        mx = fmaxf(mx, x);
    }

    __shared__ float red[32];
    for (int o = 16; o > 0; o >>= 1) mx = fmaxf(mx, __shfl_xor_sync(0xffffffffu, mx, o));
    if ((tid & 31) == 0) red[tid >> 5] = mx;
    __syncthreads();
    if (tid < 32) {
        float m2 = (tid < 8) ? red[tid] : -1e30f;
        for (int o = 4; o > 0; o >>= 1) m2 = fmaxf(m2, __shfl_xor_sync(0xffffffffu, m2, o));
        if (tid == 0) red[0] = m2;
    }
    __syncthreads();
    mx = red[0];
    __syncthreads();

    float s = 0.f;
#pragma unroll
    for (int l = 0; l < 8; l++) {
        const float e = expf(v[l] - mx);
        v[l] = e;
        s += e;
    }
    for (int o = 16; o > 0; o >>= 1) s += __shfl_xor_sync(0xffffffffu, s, o);
    if ((tid & 31) == 0) red[tid >> 5] = s;
    __syncthreads();
    if (tid < 32) {
        float s2 = (tid < 8) ? red[tid] : 0.f;
        for (int o = 4; o > 0; o >>= 1) s2 += __shfl_xor_sync(0xffffffffu, s2, o);
        if (tid == 0) red[0] = s2;
    }
    __syncthreads();
    const float inv = 1.0f / red[0];

    __half2 oh[4];
#pragma unroll
    for (int l = 0; l < 4; l++)
        oh[l] = __floats2half2_rn(v[2 * l] * inv, v[2 * l + 1] * inv);
    uint4 w;
    w.x = *(uint32_t*)&oh[0]; w.y = *(uint32_t*)&oh[1];
    w.z = *(uint32_t*)&oh[2]; w.w = *(uint32_t*)&oh[3];
    ((uint4*)p)[tid] = w;
}

// ---------------- launcher ----------------
extern "C" void kernel_launch(void* const* d_in, const int* in_sizes, int n_in,
                              void* d_out, int out_size)
{
    (void)in_sizes; (void)n_in; (void)out_size;
    const float* x    = (const float*)d_in[0];
    const int*   mask = (const int*)d_in[1];
    const float* Wq   = (const float*)d_in[2];
    const float* Wk   = (const float*)d_in[3];
    const float* Wv   = (const float*)d_in[4];
    const float* Wp   = (const float*)d_in[5];
    float* out = (float*)d_out;

    __half *hx, *hwq, *hwk, *hwv, *hwp, *hq, *hk, *hv, *hp, *hc;
    cudaGetSymbolAddress((void**)&hx,  g_x);
    cudaGetSymbolAddress((void**)&hwq, g_wq);
    cudaGetSymbolAddress((void**)&hwk, g_wk);
    cudaGetSymbolAddress((void**)&hwv, g_wv);
    cudaGetSymbolAddress((void**)&hwp, g_wp);
    cudaGetSymbolAddress((void**)&hq,  g_q);
    cudaGetSymbolAddress((void**)&hk,  g_k);
    cudaGetSymbolAddress((void**)&hv,  g_v);
    cudaGetSymbolAddress((void**)&hp,  g_p);
    cudaGetSymbolAddress((void**)&hc,  g_c);

    cudaFuncSetAttribute(gemm_h<__half>, cudaFuncAttributeMaxDynamicSharedMemorySize, SM_TOTAL);
    cudaFuncSetAttribute(gemm_h<float>,  cudaFuncAttributeMaxDynamicSharedMemorySize, SM_TOTAL);

    const long SD = (long)Sdim * Ddim;      // 1048576
    const long DD = (long)Ddim * Ddim;      // 262144
    const long SS = (long)Sdim * Sdim;      // 4194304
    const float scale = 1.0f / sqrtf((float)Ddim);
    dim3 blk(128);

    // 0) convert inputs to half
    {
        int nx = Bdim * Sdim * Ddim / 4;            // 1048576
        int nw = Hdim * Ddim * Ddim / 4;            // 524288
        f2h_kernel<<<(nx + 255) / 256, 256>>>(x,  hx,  nx);
        f2h_kernel<<<(nw + 255) / 256, 256>>>(Wq, hwq, nw);
        f2h_kernel<<<(nw + 255) / 256, 256>>>(Wk, hwk, nw);
        f2h_kernel<<<(nw + 255) / 256, 256>>>(Wv, hwv, nw);
        f2h_kernel<<<(nw + 255) / 256, 256>>>(Wp, hwp, nw);
    }

    // 1) Q,K projections: q[b,h,s,e] = x[b] @ Wq[h]^T  (M=S,N=D,K=D)
    {
        dim3 grid(Ddim / 128, Sdim / 128, Hdim * Bdim);
        gemm_h<__half><<<grid, blk, SM_TOTAL>>>(hx, hwq, hq, Ddim, Ddim, Ddim, Ddim,
                                                Bdim, 0, SD, DD, 0, SD, Hdim * SD, 1.f);
        gemm_h<__half><<<grid, blk, SM_TOTAL>>>(hx, hwk, hk, Ddim, Ddim, Ddim, Ddim,
                                                Bdim, 0, SD, DD, 0, SD, Hdim * SD, 1.f);
    }

    // 2) V^T: v_t[b,h,e,t] = Wv[h] @ x[b]^T  (M=D,N=S,K=D)
    {
        dim3 grid(Sdim / 128, Ddim / 128, Hdim * Bdim);
        gemm_h<__half><<<grid, blk, SM_TOTAL>>>(hwv, hx, hv, Ddim, Ddim, Ddim, Sdim,
                                                Bdim, DD, 0, 0, SD, SD, Hdim * SD, 1.f);
    }

    // 3) logits: L[s,t] = scale * q @ k^T  (M=N=S,K=D), z=b*H+h
    {
        dim3 grid(Sdim / 128, Sdim / 128, Bdim * Hdim);
        gemm_h<__half><<<grid, blk, SM_TOTAL>>>(hq, hk, hp, Ddim, Ddim, Ddim, Sdim,
                                                1, SD, 0, SD, 0, SS, 0, scale);
    }

    // 4) masked softmax in place (half)
    softmax_h<<<Bdim * Hdim * Sdim, 256>>>(hp, mask);

    // 5) PV: O[s,e] = P @ v_t^T  (M=S,N=D,K=S) -> concat layout
    {
        dim3 grid(Ddim / 128, Sdim / 128, Bdim * Hdim);
        gemm_h<__half><<<grid, blk, SM_TOTAL>>>(hp, hv, hc, Sdim, Sdim, Sdim,
                                                Hdim * Ddim, Hdim,
                                                (long)Hdim * SS, SS,
                                                (long)Hdim * SD, SD,
                                                (long)Sdim * Hdim * Ddim, (long)Ddim, 1.f);
    }

    // 6) out proj: y[b,s,d] = cat[b] @ Wp^T  (M=S,N=D,K=H*D), z=b
    {
        dim3 grid(Ddim / 128, Sdim / 128, Bdim);
        gemm_h<float><<<grid, blk, SM_TOTAL>>>(hc, hwp, out, Hdim * Ddim,
                                               Hdim * Ddim, Hdim * Ddim, Ddim, 1,
                                               (long)Sdim * Hdim * Ddim, 0, 0, 0,
                                               SD, 0, 1.f);
    }
}

// round 7
// speedup vs baseline: 2.7211x; 1.6753x over previous
#include <cuda_runtime.h>
#include <cuda_fp16.h>
#include <cstdint>
#include <math.h>

#define Bdim 4
#define Sdim 2048
#define Ddim 512
#define Hdim 8

// half scratch (device globals: allocation-free)
__device__ __half g_x [(size_t)Bdim * Sdim * Ddim];
__device__ __half g_wq[(size_t)Hdim * Ddim * Ddim];
__device__ __half g_wk[(size_t)Hdim * Ddim * Ddim];
__device__ __half g_wv[(size_t)Hdim * Ddim * Ddim];
__device__ __half g_wp[(size_t)Ddim * Hdim * Ddim];
__device__ __half g_q [(size_t)Bdim * Hdim * Sdim * Ddim];   // [b][h][s][e]
__device__ __half g_k [(size_t)Bdim * Hdim * Sdim * Ddim];   // [b][h][t][e]
__device__ __half g_v [(size_t)Bdim * Hdim * Sdim * Ddim];   // V^T: [b][h][e][t]
__device__ __half g_p [(size_t)Bdim * Hdim * Sdim * Sdim];   // exp(logit-4), unnormalized
__device__ __half g_c [(size_t)Bdim * Sdim * Hdim * Ddim];   // concat
__device__ float  g_rs[(size_t)Bdim * Hdim * Sdim];          // row sums

#define EXP_SHIFT 4.0f

// ---------------- fp16 mma.sync GEMM (all-NT, fp32 accum) ----------------
// C[M,N] = alpha * A[M,K] * B^T   (A: [M][K] half, B: [N][K] half, K-contig)
// CTA 128x128, 4 warps (2x2), warp tile 64x64, K-chunk 64 halves (128B rows).
// 3-stage cp.async pipeline, XOR-16B swizzle, ldmatrix.x4, m16n8k16 fp32-acc.
// EPI: 0 = plain (alpha*acc), 1 = masked exp + row-sum atomics (logits),
//      2 = divide by row sum (PV).

#define BUFS   32768                       // A tile 16KB + B tile 16KB
#define SM_TOTAL (3 * BUFS)                // 98304 bytes

__device__ __forceinline__ uint32_t smem_u32(const void* p) {
    uint32_t a;
    asm("{ .reg .u64 t; cvta.to.shared.u64 t, %1; cvt.u32.u64 %0, t; }"
        : "=r"(a) : "l"(p));
    return a;
}

__device__ __forceinline__ void cpasync16(uint32_t dst, const void* src) {
    asm volatile("cp.async.cg.shared.global [%0], [%1], 16;"
                 :: "r"(dst), "l"(src) : "memory");
}

__device__ __forceinline__ void mma16(float* c, const uint32_t* a,
                                      uint32_t b0, uint32_t b1) {
    asm volatile(
        "mma.sync.aligned.m16n8k16.row.col.f32.f16.f16.f32 "
        "{%0,%1,%2,%3}, {%4,%5,%6,%7}, {%8,%9}, {%0,%1,%2,%3};\n"
        : "+f"(c[0]), "+f"(c[1]), "+f"(c[2]), "+f"(c[3])
        : "r"(a[0]), "r"(a[1]), "r"(a[2]), "r"(a[3]), "r"(b0), "r"(b1));
}

__device__ __forceinline__ void ldm_x4(uint32_t* r, uint32_t addr) {
    asm volatile(
        "ldmatrix.sync.aligned.m8n8.x4.shared.b16 {%0,%1,%2,%3}, [%4];"
        : "=r"(r[0]), "=r"(r[1]), "=r"(r[2]), "=r"(r[3]) : "r"(addr));
}

__device__ __forceinline__ void stage_cp(uint32_t sbuf, const __half* __restrict__ g,
                                         long ld, int kofs, int tid) {
#pragma unroll
    for (int i = 0; i < 8; i++) {
        const int idx = tid + i * 128;
        const int m = idx >> 3, ch = idx & 7;
        const int sc = ch ^ (m & 7);
        cpasync16(sbuf + (uint32_t)(m * 128 + sc * 16),
                  g + (long)m * ld + kofs + ch * 8);
    }
}

__device__ __forceinline__ void store2(float* C, long off, float v0, float v1) {
    *(float2*)&C[off] = make_float2(v0, v1);
}
__device__ __forceinline__ void store2(__half* C, long off, float v0, float v1) {
    *(__half2*)&C[off] = __floats2half2_rn(v0, v1);
}

template <typename OutT, int EPI>
__global__ void __launch_bounds__(128, 2)
gemm_h(const __half* __restrict__ A, const __half* __restrict__ Bm,
       OutT* __restrict__ C,
       int K, int lda, int ldb, int ldc, int Z2,
       long sA1, long sA2, long sB1, long sB2, long sC1, long sC2,
       float alpha, const int* __restrict__ mask, float* __restrict__ rowsum)
{
    extern __shared__ __half smem[];
    const uint32_t sb = smem_u32(smem);
    const int tid = threadIdx.x;
    const int wid = tid >> 5, lane = tid & 31;
    const int g8 = lane >> 3, rr = lane & 7;
    const int wm = (wid & 1) * 64, wn = (wid >> 1) * 64;
    const int acs = g8 >> 1;
    const int bcs = g8 & 1;

    uint32_t rowA[4], rowB[4];
#pragma unroll
    for (int t = 0; t < 4; t++) {
        rowA[t] = (uint32_t)(wm + t * 16 + (g8 & 1) * 8 + rr) * 128u;
        rowB[t] = (uint32_t)(wn + t * 16 + (g8 >> 1) * 8 + rr) * 128u + 16384u;
    }

    const int z = blockIdx.z, z1 = z / Z2, z2 = z % Z2;
    A  += z1 * sA1 + z2 * sA2;
    Bm += z1 * sB1 + z2 * sB2;
    C  += z1 * sC1 + z2 * sC2;
    const int bm = blockIdx.y * 128;
    const int bn = blockIdx.x * 128;

    const __half* Ag = A + (long)bm * lda;
    const __half* Bg = Bm + (long)bn * ldb;

    float acc[4][8][4];
#pragma unroll
    for (int mt = 0; mt < 4; mt++)
#pragma unroll
        for (int nt = 0; nt < 8; nt++)
#pragma unroll
            for (int q = 0; q < 4; q++) acc[mt][nt][q] = 0.f;

    const int KC = K >> 6;

    stage_cp(sb,                 Ag, lda, 0, tid);
    stage_cp(sb + 16384u,        Bg, ldb, 0, tid);
    asm volatile("cp.async.commit_group;" ::: "memory");
    stage_cp(sb + BUFS,          Ag, lda, 64, tid);
    stage_cp(sb + BUFS + 16384u, Bg, ldb, 64, tid);
    asm volatile("cp.async.commit_group;" ::: "memory");

    int bufc = 0;
    for (int c = 0; c < KC; c++) {
        if (c + 1 < KC)
            asm volatile("cp.async.wait_group 1;" ::: "memory");
        else
            asm volatile("cp.async.wait_group 0;" ::: "memory");
        __syncthreads();

        if (c + 2 < KC) {
            int si = bufc + 2; if (si >= 3) si -= 3;
            const uint32_t ss = sb + (uint32_t)si * BUFS;
            stage_cp(ss,          Ag, lda, (c + 2) * 64, tid);
            stage_cp(ss + 16384u, Bg, ldb, (c + 2) * 64, tid);
        }
        asm volatile("cp.async.commit_group;" ::: "memory");

        const uint32_t ab = sb + (uint32_t)bufc * BUFS;
#pragma unroll
        for (int ks = 0; ks < 4; ks++) {
            const uint32_t sca = (uint32_t)(((2 * ks + acs) ^ rr) * 16);
            const uint32_t scb = (uint32_t)(((2 * ks + bcs) ^ rr) * 16);
            uint32_t a[4][4], b[4][4];
#pragma unroll
            for (int mt = 0; mt < 4; mt++) ldm_x4(a[mt], ab + rowA[mt] + sca);
#pragma unroll
            for (int np = 0; np < 4; np++) ldm_x4(b[np], ab + rowB[np] + scb);
#pragma unroll
            for (int mt = 0; mt < 4; mt++)
#pragma unroll
                for (int np = 0; np < 4; np++) {
                    mma16(acc[mt][2 * np],     a[mt], b[np][0], b[np][1]);
                    mma16(acc[mt][2 * np + 1], a[mt], b[np][2], b[np][3]);
                }
        }
        bufc++; if (bufc == 3) bufc = 0;
    }

    // ---------------- epilogue ----------------
    const int g = lane >> 2, t4 = lane & 3;

    if (EPI == 1) {
        // masked exp + row-sum atomics; C is half P
        const int* mb = mask + (long)z1 * Sdim;
        float* rs = rowsum + ((long)z1 * Hdim + z2) * (long)Sdim;
        int mc[8][2];
#pragma unroll
        for (int nt = 0; nt < 8; nt++) {
            const int c0 = bn + wn + nt * 8 + t4 * 2;
            mc[nt][0] = mb[c0];
            mc[nt][1] = mb[c0 + 1];
        }
#pragma unroll
        for (int mt = 0; mt < 4; mt++) {
            const int r0 = bm + wm + mt * 16 + g;
            const int mr0 = mb[r0], mr1 = mb[r0 + 8];
            float s0 = 0.f, s1 = 0.f;
#pragma unroll
            for (int nt = 0; nt < 8; nt++) {
                const int c0 = bn + wn + nt * 8 + t4 * 2;
                float e00 = (mr0 && mc[nt][0]) ? expf(alpha * acc[mt][nt][0] - EXP_SHIFT) : 0.f;
                float e01 = (mr0 && mc[nt][1]) ? expf(alpha * acc[mt][nt][1] - EXP_SHIFT) : 0.f;
                float e10 = (mr1 && mc[nt][0]) ? expf(alpha * acc[mt][nt][2] - EXP_SHIFT) : 0.f;
                float e11 = (mr1 && mc[nt][1]) ? expf(alpha * acc[mt][nt][3] - EXP_SHIFT) : 0.f;
                s0 += e00 + e01;
                s1 += e10 + e11;
                store2(C, (long)r0 * ldc + c0, e00, e01);
                store2(C, (long)(r0 + 8) * ldc + c0, e10, e11);
            }
            s0 += __shfl_xor_sync(0xffffffffu, s0, 1);
            s0 += __shfl_xor_sync(0xffffffffu, s0, 2);
            s1 += __shfl_xor_sync(0xffffffffu, s1, 1);
            s1 += __shfl_xor_sync(0xffffffffu, s1, 2);
            if (t4 == 0) {
                atomicAdd(&rs[r0], s0);
                atomicAdd(&rs[r0 + 8], s1);
            }
        }
    } else if (EPI == 2) {
        // divide by row sum; C is half concat
        const float* rs = rowsum + ((long)z1 * Hdim + z2) * (long)Sdim;
#pragma unroll
        for (int mt = 0; mt < 4; mt++) {
            const int r0 = bm + wm + mt * 16 + g;
            const float d0 = rs[r0], d1 = rs[r0 + 8];
            const float inv0 = (d0 > 0.f) ? 1.f / d0 : 0.f;
            const float inv1 = (d1 > 0.f) ? 1.f / d1 : 0.f;
#pragma unroll
            for (int nt = 0; nt < 8; nt++) {
                const int c0 = bn + wn + nt * 8 + t4 * 2;
                store2(C, (long)r0 * ldc + c0,
                       inv0 * acc[mt][nt][0], inv0 * acc[mt][nt][1]);
                store2(C, (long)(r0 + 8) * ldc + c0,
                       inv1 * acc[mt][nt][2], inv1 * acc[mt][nt][3]);
            }
        }
    } else {
#pragma unroll
        for (int mt = 0; mt < 4; mt++) {
#pragma unroll
            for (int nt = 0; nt < 8; nt++) {
                const int r0 = bm + wm + mt * 16 + g;
                const int c0 = bn + wn + nt * 8 + t4 * 2;
                store2(C, (long)r0 * ldc + c0,
                       alpha * acc[mt][nt][0], alpha * acc[mt][nt][1]);
                store2(C, (long)(r0 + 8) * ldc + c0,
                       alpha * acc[mt][nt][2], alpha * acc[mt][nt][3]);
            }
        }
    }
}

// ---------------- fp32 -> fp16 convert ----------------
__global__ void f2h_kernel(const float* __restrict__ in, __half* __restrict__ out,
                           int n4)
{
    int i = blockIdx.x * 256 + threadIdx.x;
    if (i < n4) {
        float4 v = ((const float4*)in)[i];
        __half2 h0 = __floats2half2_rn(v.x, v.y);
        __half2 h1 = __floats2half2_rn(v.z, v.w);
        uint2 u;
        u.x = *(uint32_t*)&h0;
        u.y = *(uint32_t*)&h1;
        ((uint2*)out)[i] = u;
    }
}

// ---------------- zero rowsums ----------------
__global__ void zero_rs(float* __restrict__ rs)
{
    rs[blockIdx.x * 256 + threadIdx.x] = 0.f;
}

// ---------------- launcher ----------------
extern "C" void kernel_launch(void* const* d_in, const int* in_sizes, int n_in,
                              void* d_out, int out_size)
{
    (void)in_sizes; (void)n_in; (void)out_size;
    const float* x    = (const float*)d_in[0];
    const int*   mask = (const int*)d_in[1];
    const float* Wq   = (const float*)d_in[2];
    const float* Wk   = (const float*)d_in[3];
    const float* Wv   = (const float*)d_in[4];
    const float* Wp   = (const float*)d_in[5];
    float* out = (float*)d_out;

    __half *hx, *hwq, *hwk, *hwv, *hwp, *hq, *hk, *hv, *hp, *hc;
    float* rs;
    cudaGetSymbolAddress((void**)&hx,  g_x);
    cudaGetSymbolAddress((void**)&hwq, g_wq);
    cudaGetSymbolAddress((void**)&hwk, g_wk);
    cudaGetSymbolAddress((void**)&hwv, g_wv);
    cudaGetSymbolAddress((void**)&hwp, g_wp);
    cudaGetSymbolAddress((void**)&hq,  g_q);
    cudaGetSymbolAddress((void**)&hk,  g_k);
    cudaGetSymbolAddress((void**)&hv,  g_v);
    cudaGetSymbolAddress((void**)&hp,  g_p);
    cudaGetSymbolAddress((void**)&hc,  g_c);
    cudaGetSymbolAddress((void**)&rs,  g_rs);

    cudaFuncSetAttribute((const void*)gemm_h<__half, 0>, cudaFuncAttributeMaxDynamicSharedMemorySize, SM_TOTAL);
    cudaFuncSetAttribute((const void*)gemm_h<__half, 1>, cudaFuncAttributeMaxDynamicSharedMemorySize, SM_TOTAL);
    cudaFuncSetAttribute((const void*)gemm_h<__half, 2>, cudaFuncAttributeMaxDynamicSharedMemorySize, SM_TOTAL);
    cudaFuncSetAttribute((const void*)gemm_h<float, 0>,  cudaFuncAttributeMaxDynamicSharedMemorySize, SM_TOTAL);

    const long SD = (long)Sdim * Ddim;      // 1048576
    const long DD = (long)Ddim * Ddim;      // 262144
    const long SS = (long)Sdim * Sdim;      // 4194304
    const float scale = 1.0f / sqrtf((float)Ddim);
    dim3 blk(128);

    // 0) convert inputs to half + zero rowsums
    {
        int nx = Bdim * Sdim * Ddim / 4;
        int nw = Hdim * Ddim * Ddim / 4;
        f2h_kernel<<<(nx + 255) / 256, 256>>>(x,  hx,  nx);
        f2h_kernel<<<(nw + 255) / 256, 256>>>(Wq, hwq, nw);
        f2h_kernel<<<(nw + 255) / 256, 256>>>(Wk, hwk, nw);
        f2h_kernel<<<(nw + 255) / 256, 256>>>(Wv, hwv, nw);
        f2h_kernel<<<(nw + 255) / 256, 256>>>(Wp, hwp, nw);
        zero_rs<<<Bdim * Hdim * Sdim / 256, 256>>>(rs);
    }

    // 1) Q,K projections (M=S,N=D,K=D), z1=h (Z2=B), z2=b
    {
        dim3 grid(Ddim / 128, Sdim / 128, Hdim * Bdim);
        gemm_h<__half, 0><<<grid, blk, SM_TOTAL>>>(hx, hwq, hq, Ddim, Ddim, Ddim, Ddim,
                                                   Bdim, 0, SD, DD, 0, SD, Hdim * SD,
                                                   1.f, nullptr, nullptr);
        gemm_h<__half, 0><<<grid, blk, SM_TOTAL>>>(hx, hwk, hk, Ddim, Ddim, Ddim, Ddim,
                                                   Bdim, 0, SD, DD, 0, SD, Hdim * SD,
                                                   1.f, nullptr, nullptr);
    }

    // 2) V^T: v_t[b,h,e,t] = Wv[h] @ x[b]^T  (M=D,N=S,K=D)
    {
        dim3 grid(Sdim / 128, Ddim / 128, Hdim * Bdim);
        gemm_h<__half, 0><<<grid, blk, SM_TOTAL>>>(hwv, hx, hv, Ddim, Ddim, Ddim, Sdim,
                                                   Bdim, DD, 0, 0, SD, SD, Hdim * SD,
                                                   1.f, nullptr, nullptr);
    }

    // 3) logits + masked exp + rowsum (M=N=S,K=D); z1=b (Z2=H), z2=h
    {
        dim3 grid(Sdim / 128, Sdim / 128, Bdim * Hdim);
        gemm_h<__half, 1><<<grid, blk, SM_TOTAL>>>(hq, hk, hp, Ddim, Ddim, Ddim, Sdim,
                                                   Hdim, Hdim * SD, SD, Hdim * SD, SD,
                                                   Hdim * SS, SS,
                                                   scale, mask, rs);
    }

    // 4) PV with rowsum normalization (M=S,N=D,K=S) -> concat; z1=b, z2=h
    {
        dim3 grid(Ddim / 128, Sdim / 128, Bdim * Hdim);
        gemm_h<__half, 2><<<grid, blk, SM_TOTAL>>>(hp, hv, hc, Sdim, Sdim, Sdim,
                                                   Hdim * Ddim, Hdim,
                                                   (long)Hdim * SS, SS,
                                                   (long)Hdim * SD, SD,
                                                   (long)Sdim * Hdim * Ddim, (long)Ddim,
                                                   1.f, nullptr, rs);
    }

    // 5) out proj (M=S,N=D,K=H*D), z=b
    {
        dim3 grid(Ddim / 128, Sdim / 128, Bdim);
        gemm_h<float, 0><<<grid, blk, SM_TOTAL>>>(hc, hwp, out, Hdim * Ddim,
                                                  Hdim * Ddim, Hdim * Ddim, Ddim, 1,
                                                  (long)Sdim * Hdim * Ddim, 0, 0, 0,
                                                  SD, 0, 1.f, nullptr, nullptr);
    }
}

// round 8
// speedup vs baseline: 2.7661x; 1.0165x over previous
#include <cuda_runtime.h>
#include <cuda_fp16.h>
#include <cstdint>
#include <math.h>

#define Bdim 4
#define Sdim 2048
#define Ddim 512
#define Hdim 8

// half scratch (device globals: allocation-free)
__device__ __half g_x [(size_t)Bdim * Sdim * Ddim];
__device__ __half g_wq[(size_t)Hdim * Ddim * Ddim];
__device__ __half g_wk[(size_t)Hdim * Ddim * Ddim];
__device__ __half g_wv[(size_t)Hdim * Ddim * Ddim];
__device__ __half g_wp[(size_t)Ddim * Hdim * Ddim];
__device__ __half g_q [(size_t)Bdim * Hdim * Sdim * Ddim];   // [b][h][s][e]
__device__ __half g_k [(size_t)Bdim * Hdim * Sdim * Ddim];   // [b][h][t][e]
__device__ __half g_v [(size_t)Bdim * Hdim * Sdim * Ddim];   // V^T: [b][h][e][t]
__device__ __half g_p [(size_t)Bdim * Hdim * Sdim * Sdim];   // exp(logit-4), unnormalized
__device__ __half g_c [(size_t)Bdim * Sdim * Hdim * Ddim];   // concat
__device__ float  g_rs[(size_t)Bdim * Hdim * Sdim];          // row sums

#define EXP_SHIFT 4.0f

// ---------------- fp16 mma.sync GEMM (all-NT, fp32 accum) ----------------
// C[M,N] = alpha * A[M,K] * B^T   (A: [M][K] half, B: [N][K] half, K-contig)
// CTA 128x128, 256 threads (8 warps, 4x2), warp tile 32x64.
// K-chunk 64 halves, 3-stage cp.async pipeline, XOR-16B swizzle,
// ldmatrix.x4, m16n8k16 fp32-acc. 16 warps/SM at 2 CTAs/SM.
// EPI: 0 = plain, 1 = masked exp + row-sum atomics, 2 = rowsum normalize.

#define BUFS   32768                       // A tile 16KB + B tile 16KB
#define SM_TOTAL (3 * BUFS)                // 98304 bytes

__device__ __forceinline__ uint32_t smem_u32(const void* p) {
    uint32_t a;
    asm("{ .reg .u64 t; cvta.to.shared.u64 t, %1; cvt.u32.u64 %0, t; }"
        : "=r"(a) : "l"(p));
    return a;
}

__device__ __forceinline__ void cpasync16(uint32_t dst, const void* src) {
    asm volatile("cp.async.cg.shared.global [%0], [%1], 16;"
                 :: "r"(dst), "l"(src) : "memory");
}

__device__ __forceinline__ void mma16(float* c, const uint32_t* a,
                                      uint32_t b0, uint32_t b1) {
    asm volatile(
        "mma.sync.aligned.m16n8k16.row.col.f32.f16.f16.f32 "
        "{%0,%1,%2,%3}, {%4,%5,%6,%7}, {%8,%9}, {%0,%1,%2,%3};\n"
        : "+f"(c[0]), "+f"(c[1]), "+f"(c[2]), "+f"(c[3])
        : "r"(a[0]), "r"(a[1]), "r"(a[2]), "r"(a[3]), "r"(b0), "r"(b1));
}

__device__ __forceinline__ void ldm_x4(uint32_t* r, uint32_t addr) {
    asm volatile(
        "ldmatrix.sync.aligned.m8n8.x4.shared.b16 {%0,%1,%2,%3}, [%4];"
        : "=r"(r[0]), "=r"(r[1]), "=r"(r[2]), "=r"(r[3]) : "r"(addr));
}

// stage one 128row x 64half tile via 4 cp.async.16B per thread (256 thr)
__device__ __forceinline__ void stage_cp(uint32_t sbuf, const __half* __restrict__ g,
                                         long ld, int kofs, int tid) {
#pragma unroll
    for (int i = 0; i < 4; i++) {
        const int idx = tid + i * 256;
        const int m = idx >> 3, ch = idx & 7;
        const int sc = ch ^ (m & 7);
        cpasync16(sbuf + (uint32_t)(m * 128 + sc * 16),
                  g + (long)m * ld + kofs + ch * 8);
    }
}

__device__ __forceinline__ void store2(float* C, long off, float v0, float v1) {
    *(float2*)&C[off] = make_float2(v0, v1);
}
__device__ __forceinline__ void store2(__half* C, long off, float v0, float v1) {
    *(__half2*)&C[off] = __floats2half2_rn(v0, v1);
}

template <typename OutT, int EPI>
__global__ void __launch_bounds__(256, 2)
gemm_h(const __half* __restrict__ A, const __half* __restrict__ Bm,
       OutT* __restrict__ C,
       int K, int lda, int ldb, int ldc, int Z2,
       long sA1, long sA2, long sB1, long sB2, long sC1, long sC2,
       float alpha, const int* __restrict__ mask, float* __restrict__ rowsum)
{
    extern __shared__ __half smem[];
    const uint32_t sb = smem_u32(smem);
    const int tid = threadIdx.x;
    const int wid = tid >> 5, lane = tid & 31;
    const int g8 = lane >> 3, rr = lane & 7;
    const int wm = (wid & 3) * 32, wn = (wid >> 2) * 64;
    const int acs = g8 >> 1;
    const int bcs = g8 & 1;

    uint32_t rowA[2], rowB[4];
#pragma unroll
    for (int t = 0; t < 2; t++)
        rowA[t] = (uint32_t)(wm + t * 16 + (g8 & 1) * 8 + rr) * 128u;
#pragma unroll
    for (int t = 0; t < 4; t++)
        rowB[t] = (uint32_t)(wn + t * 16 + (g8 >> 1) * 8 + rr) * 128u + 16384u;

    const int z = blockIdx.z, z1 = z / Z2, z2 = z % Z2;
    A  += z1 * sA1 + z2 * sA2;
    Bm += z1 * sB1 + z2 * sB2;
    C  += z1 * sC1 + z2 * sC2;
    const int bm = blockIdx.y * 128;
    const int bn = blockIdx.x * 128;

    const __half* Ag = A + (long)bm * lda;
    const __half* Bg = Bm + (long)bn * ldb;

    float acc[2][8][4];
#pragma unroll
    for (int mt = 0; mt < 2; mt++)
#pragma unroll
        for (int nt = 0; nt < 8; nt++)
#pragma unroll
            for (int q = 0; q < 4; q++) acc[mt][nt][q] = 0.f;

    const int KC = K >> 6;

    stage_cp(sb,                 Ag, lda, 0, tid);
    stage_cp(sb + 16384u,        Bg, ldb, 0, tid);
    asm volatile("cp.async.commit_group;" ::: "memory");
    stage_cp(sb + BUFS,          Ag, lda, 64, tid);
    stage_cp(sb + BUFS + 16384u, Bg, ldb, 64, tid);
    asm volatile("cp.async.commit_group;" ::: "memory");

    int bufc = 0;
    for (int c = 0; c < KC; c++) {
        if (c + 1 < KC)
            asm volatile("cp.async.wait_group 1;" ::: "memory");
        else
            asm volatile("cp.async.wait_group 0;" ::: "memory");
        __syncthreads();

        if (c + 2 < KC) {
            int si = bufc + 2; if (si >= 3) si -= 3;
            const uint32_t ss = sb + (uint32_t)si * BUFS;
            stage_cp(ss,          Ag, lda, (c + 2) * 64, tid);
            stage_cp(ss + 16384u, Bg, ldb, (c + 2) * 64, tid);
        }
        asm volatile("cp.async.commit_group;" ::: "memory");

        const uint32_t ab = sb + (uint32_t)bufc * BUFS;
#pragma unroll
        for (int ks = 0; ks < 4; ks++) {
            const uint32_t sca = (uint32_t)(((2 * ks + acs) ^ rr) * 16);
            const uint32_t scb = (uint32_t)(((2 * ks + bcs) ^ rr) * 16);
            uint32_t a[2][4], b[4][4];
#pragma unroll
            for (int mt = 0; mt < 2; mt++) ldm_x4(a[mt], ab + rowA[mt] + sca);
#pragma unroll
            for (int np = 0; np < 4; np++) ldm_x4(b[np], ab + rowB[np] + scb);
#pragma unroll
            for (int mt = 0; mt < 2; mt++)
#pragma unroll
                for (int np = 0; np < 4; np++) {
                    mma16(acc[mt][2 * np],     a[mt], b[np][0], b[np][1]);
                    mma16(acc[mt][2 * np + 1], a[mt], b[np][2], b[np][3]);
                }
        }
        bufc++; if (bufc == 3) bufc = 0;
    }

    // ---------------- epilogue ----------------
    const int g = lane >> 2, t4 = lane & 3;

    if (EPI == 1) {
        const int* mb = mask + (long)z1 * Sdim;
        float* rs = rowsum + ((long)z1 * Hdim + z2) * (long)Sdim;
        int mc[8][2];
#pragma unroll
        for (int nt = 0; nt < 8; nt++) {
            const int c0 = bn + wn + nt * 8 + t4 * 2;
            mc[nt][0] = mb[c0];
            mc[nt][1] = mb[c0 + 1];
        }
#pragma unroll
        for (int mt = 0; mt < 2; mt++) {
            const int r0 = bm + wm + mt * 16 + g;
            const int mr0 = mb[r0], mr1 = mb[r0 + 8];
            float s0 = 0.f, s1 = 0.f;
#pragma unroll
            for (int nt = 0; nt < 8; nt++) {
                const int c0 = bn + wn + nt * 8 + t4 * 2;
                float e00 = (mr0 && mc[nt][0]) ? expf(alpha * acc[mt][nt][0] - EXP_SHIFT) : 0.f;
                float e01 = (mr0 && mc[nt][1]) ? expf(alpha * acc[mt][nt][1] - EXP_SHIFT) : 0.f;
                float e10 = (mr1 && mc[nt][0]) ? expf(alpha * acc[mt][nt][2] - EXP_SHIFT) : 0.f;
                float e11 = (mr1 && mc[nt][1]) ? expf(alpha * acc[mt][nt][3] - EXP_SHIFT) : 0.f;
                s0 += e00 + e01;
                s1 += e10 + e11;
                store2(C, (long)r0 * ldc + c0, e00, e01);
                store2(C, (long)(r0 + 8) * ldc + c0, e10, e11);
            }
            s0 += __shfl_xor_sync(0xffffffffu, s0, 1);
            s0 += __shfl_xor_sync(0xffffffffu, s0, 2);
            s1 += __shfl_xor_sync(0xffffffffu, s1, 1);
            s1 += __shfl_xor_sync(0xffffffffu, s1, 2);
            if (t4 == 0) {
                atomicAdd(&rs[r0], s0);
                atomicAdd(&rs[r0 + 8], s1);
            }
        }
    } else if (EPI == 2) {
        const float* rs = rowsum + ((long)z1 * Hdim + z2) * (long)Sdim;
#pragma unroll
        for (int mt = 0; mt < 2; mt++) {
            const int r0 = bm + wm + mt * 16 + g;
            const float d0 = rs[r0], d1 = rs[r0 + 8];
            const float inv0 = (d0 > 0.f) ? 1.f / d0 : 0.f;
            const float inv1 = (d1 > 0.f) ? 1.f / d1 : 0.f;
#pragma unroll
            for (int nt = 0; nt < 8; nt++) {
                const int c0 = bn + wn + nt * 8 + t4 * 2;
                store2(C, (long)r0 * ldc + c0,
                       inv0 * acc[mt][nt][0], inv0 * acc[mt][nt][1]);
                store2(C, (long)(r0 + 8) * ldc + c0,
                       inv1 * acc[mt][nt][2], inv1 * acc[mt][nt][3]);
            }
        }
    } else {
#pragma unroll
        for (int mt = 0; mt < 2; mt++) {
#pragma unroll
            for (int nt = 0; nt < 8; nt++) {
                const int r0 = bm + wm + mt * 16 + g;
                const int c0 = bn + wn + nt * 8 + t4 * 2;
                store2(C, (long)r0 * ldc + c0,
                       alpha * acc[mt][nt][0], alpha * acc[mt][nt][1]);
                store2(C, (long)(r0 + 8) * ldc + c0,
                       alpha * acc[mt][nt][2], alpha * acc[mt][nt][3]);
            }
        }
    }
}

// ---------------- fp32 -> fp16 convert ----------------
__global__ void f2h_kernel(const float* __restrict__ in, __half* __restrict__ out,
                           int n4)
{
    int i = blockIdx.x * 256 + threadIdx.x;
    if (i < n4) {
        float4 v = ((const float4*)in)[i];
        __half2 h0 = __floats2half2_rn(v.x, v.y);
        __half2 h1 = __floats2half2_rn(v.z, v.w);
        uint2 u;
        u.x = *(uint32_t*)&h0;
        u.y = *(uint32_t*)&h1;
        ((uint2*)out)[i] = u;
    }
}

// ---------------- zero rowsums ----------------
__global__ void zero_rs(float* __restrict__ rs)
{
    rs[blockIdx.x * 256 + threadIdx.x] = 0.f;
}

// ---------------- launcher ----------------
extern "C" void kernel_launch(void* const* d_in, const int* in_sizes, int n_in,
                              void* d_out, int out_size)
{
    (void)in_sizes; (void)n_in; (void)out_size;
    const float* x    = (const float*)d_in[0];
    const int*   mask = (const int*)d_in[1];
    const float* Wq   = (const float*)d_in[2];
    const float* Wk   = (const float*)d_in[3];
    const float* Wv   = (const float*)d_in[4];
    const float* Wp   = (const float*)d_in[5];
    float* out = (float*)d_out;

    __half *hx, *hwq, *hwk, *hwv, *hwp, *hq, *hk, *hv, *hp, *hc;
    float* rs;
    cudaGetSymbolAddress((void**)&hx,  g_x);
    cudaGetSymbolAddress((void**)&hwq, g_wq);
    cudaGetSymbolAddress((void**)&hwk, g_wk);
    cudaGetSymbolAddress((void**)&hwv, g_wv);
    cudaGetSymbolAddress((void**)&hwp, g_wp);
    cudaGetSymbolAddress((void**)&hq,  g_q);
    cudaGetSymbolAddress((void**)&hk,  g_k);
    cudaGetSymbolAddress((void**)&hv,  g_v);
    cudaGetSymbolAddress((void**)&hp,  g_p);
    cudaGetSymbolAddress((void**)&hc,  g_c);
    cudaGetSymbolAddress((void**)&rs,  g_rs);

    cudaFuncSetAttribute((const void*)gemm_h<__half, 0>, cudaFuncAttributeMaxDynamicSharedMemorySize, SM_TOTAL);
    cudaFuncSetAttribute((const void*)gemm_h<__half, 1>, cudaFuncAttributeMaxDynamicSharedMemorySize, SM_TOTAL);
    cudaFuncSetAttribute((const void*)gemm_h<__half, 2>, cudaFuncAttributeMaxDynamicSharedMemorySize, SM_TOTAL);
    cudaFuncSetAttribute((const void*)gemm_h<float, 0>,  cudaFuncAttributeMaxDynamicSharedMemorySize, SM_TOTAL);

    const long SD = (long)Sdim * Ddim;      // 1048576
    const long DD = (long)Ddim * Ddim;      // 262144
    const long SS = (long)Sdim * Sdim;      // 4194304
    const float scale = 1.0f / sqrtf((float)Ddim);
    dim3 blk(256);

    // 0) convert inputs to half + zero rowsums
    {
        int nx = Bdim * Sdim * Ddim / 4;
        int nw = Hdim * Ddim * Ddim / 4;
        f2h_kernel<<<(nx + 255) / 256, 256>>>(x,  hx,  nx);
        f2h_kernel<<<(nw + 255) / 256, 256>>>(Wq, hwq, nw);
        f2h_kernel<<<(nw + 255) / 256, 256>>>(Wk, hwk, nw);
        f2h_kernel<<<(nw + 255) / 256, 256>>>(Wv, hwv, nw);
        f2h_kernel<<<(nw + 255) / 256, 256>>>(Wp, hwp, nw);
        zero_rs<<<Bdim * Hdim * Sdim / 256, 256>>>(rs);
    }

    // 1) Q,K projections (M=S,N=D,K=D), z1=h (Z2=B), z2=b
    {
        dim3 grid(Ddim / 128, Sdim / 128, Hdim * Bdim);
        gemm_h<__half, 0><<<grid, blk, SM_TOTAL>>>(hx, hwq, hq, Ddim, Ddim, Ddim, Ddim,
                                                   Bdim, 0, SD, DD, 0, SD, Hdim * SD,
                                                   1.f, nullptr, nullptr);
        gemm_h<__half, 0><<<grid, blk, SM_TOTAL>>>(hx, hwk, hk, Ddim, Ddim, Ddim, Ddim,
                                                   Bdim, 0, SD, DD, 0, SD, Hdim * SD,
                                                   1.f, nullptr, nullptr);
    }

    // 2) V^T: v_t[b,h,e,t] = Wv[h] @ x[b]^T  (M=D,N=S,K=D)
    {
        dim3 grid(Sdim / 128, Ddim / 128, Hdim * Bdim);
        gemm_h<__half, 0><<<grid, blk, SM_TOTAL>>>(hwv, hx, hv, Ddim, Ddim, Ddim, Sdim,
                                                   Bdim, DD, 0, 0, SD, SD, Hdim * SD,
                                                   1.f, nullptr, nullptr);
    }

    // 3) logits + masked exp + rowsum (M=N=S,K=D); z1=b (Z2=H), z2=h
    {
        dim3 grid(Sdim / 128, Sdim / 128, Bdim * Hdim);
        gemm_h<__half, 1><<<grid, blk, SM_TOTAL>>>(hq, hk, hp, Ddim, Ddim, Ddim, Sdim,
                                                   Hdim, Hdim * SD, SD, Hdim * SD, SD,
                                                   Hdim * SS, SS,
                                                   scale, mask, rs);
    }

    // 4) PV with rowsum normalization (M=S,N=D,K=S) -> concat; z1=b, z2=h
    {
        dim3 grid(Ddim / 128, Sdim / 128, Bdim * Hdim);
        gemm_h<__half, 2><<<grid, blk, SM_TOTAL>>>(hp, hv, hc, Sdim, Sdim, Sdim,
                                                   Hdim * Ddim, Hdim,
                                                   (long)Hdim * SS, SS,
                                                   (long)Hdim * SD, SD,
                                                   (long)Sdim * Hdim * Ddim, (long)Ddim,
                                                   1.f, nullptr, rs);
    }

    // 5) out proj (M=S,N=D,K=H*D), z=b
    {
        dim3 grid(Ddim / 128, Sdim / 128, Bdim);
        gemm_h<float, 0><<<grid, blk, SM_TOTAL>>>(hc, hwp, out, Hdim * Ddim,
                                                  Hdim * Ddim, Hdim * Ddim, Ddim, 1,
                                                  (long)Sdim * Hdim * Ddim, 0, 0, 0,
                                                  SD, 0, 1.f, nullptr, nullptr);
    }
}